// round 17
// baseline (speedup 1.0000x reference)
#include <cuda_runtime.h>
#include <cuda_fp16.h>
#include <math.h>
#include <stdint.h>

// Problem constants
#define BB   32
#define SS   512
#define DD   1024
#define EE   4096          // 4*D
#define NBLK 128           // recurrence CTAs (all co-resident, 1/SM)

typedef unsigned long long u64;

// ---------- scratch (static __device__: no runtime allocation) ----------
__device__ __align__(16) float g_xp[(size_t)SS * BB * EE];       // x_proj [s][b][e]
__device__ __align__(16) __half g_Xh [(size_t)BB * SS * DD];     // X fp16
__device__ __align__(16) __half g_Uth[(size_t)EE * DD];          // U^T fp16 [e][k]
__device__ __align__(16) __half g_hT[2][DD * BB];                // h fp16 TRANSPOSED [par][d][b]
__device__ u64 g_bar;                                            // init barrier (monotonic)
__device__ u64 g_flag[NBLK][16];                                 // per-CTA step flags, 128B pad

__device__ __forceinline__ uint32_t smem_u32(const void* p) {
    uint32_t a;
    asm("{ .reg .u64 t; cvta.to.shared.u64 t, %1; cvt.u32.u64 %0, t; }" : "=r"(a) : "l"(p));
    return a;
}

__device__ __forceinline__ float sigf(float x) {
    float e = __expf(-x);
    float y; asm("rcp.approx.f32 %0, %1;" : "=f"(y) : "f"(1.0f + e));
    return y;
}

__device__ __forceinline__ float tanhf_fast(float x) {
    float e = __expf(2.0f * x);
    return 1.0f - __fdividef(2.0f, e + 1.0f);   // exact limits at +/-inf
}

__device__ __forceinline__ uint32_t pack_hf2(float a, float b) {
    __half h0 = __float2half_rn(a), h1 = __float2half_rn(b);
    uint16_t u0, u1;
    memcpy(&u0, &h0, 2); memcpy(&u1, &h1, 2);
    return (uint32_t)u0 | ((uint32_t)u1 << 16);
}

#define LDMATRIX_X4(a0, a1, a2, a3, addr) \
    asm volatile("ldmatrix.sync.aligned.m8n8.x4.shared.b16 {%0,%1,%2,%3}, [%4];" \
                 : "=r"(a0), "=r"(a1), "=r"(a2), "=r"(a3) : "r"(addr))

#define LDMATRIX_X4_TRANS(a0, a1, a2, a3, addr) \
    asm volatile("ldmatrix.sync.aligned.m8n8.x4.trans.shared.b16 {%0,%1,%2,%3}, [%4];" \
                 : "=r"(a0), "=r"(a1), "=r"(a2), "=r"(a3) : "r"(addr))

#define MMA_FP16(c, a0, a1, a2, a3, b0, b1) \
    asm volatile("mma.sync.aligned.m16n8k16.row.col.f32.f16.f16.f32 " \
                 "{%0,%1,%2,%3}, {%4,%5,%6,%7}, {%8,%9}, {%0,%1,%2,%3};" \
                 : "+f"((c)[0]), "+f"((c)[1]), "+f"((c)[2]), "+f"((c)[3]) \
                 : "r"(a0), "r"(a1), "r"(a2), "r"(a3), "r"(b0), "r"(b1))

// =====================================================================
// Prep 1: X (fp32) -> fp16, same layout (m=b*512+s rows)
// =====================================================================
__global__ void __launch_bounds__(256) splitX_kernel(const float* __restrict__ X)
{
    size_t i = ((size_t)blockIdx.x * 256 + threadIdx.x) * 4;
    float4 v = *(const float4*)(X + i);
    __half2 p01, p23;
    p01.x = __float2half_rn(v.x); p01.y = __float2half_rn(v.y);
    p23.x = __float2half_rn(v.z); p23.y = __float2half_rn(v.w);
    *(__half2*)(g_Xh + i)     = p01;
    *(__half2*)(g_Xh + i + 2) = p23;
}

// =====================================================================
// Prep 2: transpose U -> fp16: g_Uth[e=gate*1024+col][k] = Ugate[k][col]
// =====================================================================
__global__ void __launch_bounds__(256) transU_kernel(
    const float* __restrict__ Ui, const float* __restrict__ Uf,
    const float* __restrict__ Uo, const float* __restrict__ Ug)
{
    __shared__ float t[32][33];
    const int gate = blockIdx.z;
    const float* U = (gate == 0) ? Ui : (gate == 1) ? Uf : (gate == 2) ? Uo : Ug;
    const int col0 = blockIdx.x * 32;
    const int k0   = blockIdx.y * 32;
    const int tx = threadIdx.x & 31, ty = threadIdx.x >> 5;

    #pragma unroll
    for (int rr = 0; rr < 4; rr++)
        t[ty + rr * 8][tx] = U[(size_t)(k0 + ty + rr * 8) * 1024 + col0 + tx];
    __syncthreads();
    #pragma unroll
    for (int rr = 0; rr < 4; rr++) {
        int c = ty + rr * 8;
        g_Uth[(size_t)(gate * 1024 + col0 + c) * 1024 + k0 + tx] =
            __float2half_rn(t[tx][c]);
    }
}

// =====================================================================
// Kernel 1: x_proj via HMMA fp16 (single pass). CTA 128m x 64n, 8 warps.
// =====================================================================
#define XJ_SMEM ((128 + 64) * 72 * 2)

__global__ void __launch_bounds__(256) xproj_mma(
    const float* __restrict__ bi, const float* __restrict__ bf_,
    const float* __restrict__ bo, const float* __restrict__ bg)
{
    extern __shared__ __half xsm[];
    __half* Ah = xsm;                 // [128][72]
    __half* Bh = Ah + 128 * 72;       // [64][72]

    const int tid  = threadIdx.x;
    const int wid  = tid >> 5;
    const int lane = tid & 31;
    const int n0   = blockIdx.x * 64;
    const int m0   = blockIdx.y * 128;
    const int gate = n0 >> 10;
    const float* bp = (gate == 0) ? bi : (gate == 1) ? bf_ : (gate == 2) ? bo : bg;

    const int mi2 = wid & 3;
    const int nh2 = wid >> 2;

    const uint32_t AhU = smem_u32(Ah);
    const uint32_t BhU = smem_u32(Bh);

    float c[2][4][4];
    #pragma unroll
    for (int mi = 0; mi < 2; mi++)
        #pragma unroll
        for (int nb = 0; nb < 4; nb++)
            #pragma unroll
            for (int q = 0; q < 4; q++) c[mi][nb][q] = 0.0f;

    for (int kc = 0; kc < 1024; kc += 64) {
        __syncthreads();
        #pragma unroll
        for (int it = 0; it < 4; it++) {
            int idx = it * 256 + tid;
            int row = idx >> 3, k8 = idx & 7;
            size_t src = (size_t)(m0 + row) * 1024 + kc + k8 * 8;
            *(uint4*)&Ah[row * 72 + k8 * 8] = *(const uint4*)&g_Xh[src];
        }
        {
            int idx = tid;
            int row = idx >> 3, k8 = idx & 7;
            size_t src = (size_t)(n0 + row) * 1024 + kc + k8 * 8;
            *(uint4*)&Bh[row * 72 + k8 * 8] = *(const uint4*)&g_Uth[src];
            idx = 256 + tid;
            row = idx >> 3; k8 = idx & 7;
            src = (size_t)(n0 + row) * 1024 + kc + k8 * 8;
            *(uint4*)&Bh[row * 72 + k8 * 8] = *(const uint4*)&g_Uth[src];
        }
        __syncthreads();

        #pragma unroll
        for (int k16 = 0; k16 < 4; k16++) {
            const int kcol = k16 * 16;
            uint32_t ah[2][4], bh[2][4];
            #pragma unroll
            for (int mi = 0; mi < 2; mi++) {
                uint32_t off = (uint32_t)(((mi2 * 32 + mi * 16 + (lane & 15)) * 72
                                           + kcol + (lane >> 4) * 8) * 2);
                LDMATRIX_X4(ah[mi][0], ah[mi][1], ah[mi][2], ah[mi][3], AhU + off);
            }
            #pragma unroll
            for (int nb2 = 0; nb2 < 2; nb2++) {
                int rowb = nh2 * 32 + nb2 * 16 + ((lane >> 4) << 3) + (lane & 7);
                int koff = kcol + ((lane >> 3) & 1) * 8;
                uint32_t off = (uint32_t)((rowb * 72 + koff) * 2);
                LDMATRIX_X4(bh[nb2][0], bh[nb2][1], bh[nb2][2], bh[nb2][3], BhU + off);
            }
            #pragma unroll
            for (int mi = 0; mi < 2; mi++)
                #pragma unroll
                for (int nb = 0; nb < 4; nb++) {
                    uint32_t b0 = bh[nb >> 1][(nb & 1) * 2];
                    uint32_t b1 = bh[nb >> 1][(nb & 1) * 2 + 1];
                    MMA_FP16(c[mi][nb], ah[mi][0], ah[mi][1], ah[mi][2], ah[mi][3], b0, b1);
                }
        }
    }

    #pragma unroll
    for (int mi = 0; mi < 2; mi++)
        #pragma unroll
        for (int nb = 0; nb < 4; nb++) {
            int e_loc = nh2 * 32 + nb * 8 + (lane & 3) * 2;
            float bias0 = bp[(n0 & 1023) + e_loc];
            float bias1 = bp[(n0 & 1023) + e_loc + 1];
            #pragma unroll
            for (int h = 0; h < 2; h++) {
                int m = m0 + mi2 * 32 + mi * 16 + (lane >> 2) + h * 8;
                int s = m & 511, b = m >> 9;
                float2 v = {c[mi][nb][h * 2] + bias0, c[mi][nb][h * 2 + 1] + bias1};
                *(float2*)&g_xp[((size_t)s * BB + b) * EE + n0 + e_loc] = v;
            }
        }
}

// =====================================================================
// Kernel 2: HMMA recurrence, warp-specialized, transposed h exchange,
// SINGLE-DISCOVERY producer protocol.
// 128 persistent CTAs x 512 threads. CTA owns 32 z-cols (4 gates x 8 d).
// Producer warp ks: lanes 0-15 poll all 16 producer flags concurrently
// (nanosleep backoff), then ONE LDG round (16 u4/lane, MLP16) covering
// both phases; STS ph0 / bar / STS ph1 / bar keeps consumer head start.
// SMEM: sT [1024][40] half (81920) + red [2][8][32][33] f32 (67584)
// =====================================================================
#define T_STRIDE 40
#define RED_PAR  (8 * 32 * 33)
#define REC_SMEM_BYTES (1024 * T_STRIDE * 2 + 2 * RED_PAR * 4)

__global__ void __launch_bounds__(512, 1) lstm_rec_mma(
    const float* __restrict__ Wi, const float* __restrict__ Wf,
    const float* __restrict__ Wo, const float* __restrict__ Wg,
    float* __restrict__ out)
{
    extern __shared__ char sm[];
    __half* sT = (__half*)sm;                                  // [1024][40]
    float* red = (float*)(sm + 1024 * T_STRIDE * 2);           // [2][8][32][33]

    const int tid  = threadIdx.x;
    const int wid  = tid >> 5;
    const int lane = tid & 31;
    const int d0   = blockIdx.x * 8;
    const uint32_t sT_u = smem_u32(sT);

    // ---- init: zero h_{-1} (buffer 1) slice (producers), reset flag ----
    if (tid >= 256) {
        int zgb = tid & 31, zgdl = (tid >> 5) & 7;
        g_hT[1][(d0 + zgdl) * 32 + zgb] = __float2half(0.0f);
    }
    if (tid == 0) g_flag[blockIdx.x][0] = 0ULL;

    __threadfence();
    __syncthreads();

    // ---- initial full grid barrier (monotonic counter, epoch-derived) ----
    if (tid == 0) {
        u64 old = atomicAdd(&g_bar, 1ULL);
        u64 bs  = old - (old & (u64)(NBLK - 1));
        u64 tgt = bs + NBLK;
        while (*((volatile u64*)&g_bar) < tgt) { }
        __threadfence();
    }
    __syncthreads();

    if (wid < 8) {
        // ================= CONSUMER: MMA warps =================
        const int ks = wid;
        const int kbase = ks << 7;

        // W fragments: j = ni*8 + (lane>>2), gate = ni
        uint32_t Wfr[8][4][2];
        {
            const float* Wm[4] = {Wi, Wf, Wo, Wg};
            #pragma unroll
            for (int k16 = 0; k16 < 8; k16++)
                #pragma unroll
                for (int ni = 0; ni < 4; ni++)
                    #pragma unroll
                    for (int r = 0; r < 2; r++) {
                        int k0 = kbase + k16 * 16 + (lane & 3) * 2 + r * 8;
                        const float* wp = Wm[ni] + (size_t)k0 * 1024 + d0 + (lane >> 2);
                        Wfr[k16][ni][r] = pack_hf2(__ldg(wp), __ldg(wp + 1024));
                    }
        }

        // A-fragment ldmatrix.trans addressing (constant per lane)
        const int a_krow = ((lane >> 4) & 1) * 8 + (lane & 7);
        const int a_mh   = ((lane >> 3) & 1) * 8;

        for (int s = 0; s < SS; s++) {
            const int wpar = s & 1;
            float c[2][4][4];
            #pragma unroll
            for (int mi = 0; mi < 2; mi++)
                #pragma unroll
                for (int ni = 0; ni < 4; ni++)
                    #pragma unroll
                    for (int q = 0; q < 4; q++) c[mi][ni][q] = 0.0f;

            #pragma unroll
            for (int ph = 0; ph < 2; ph++) {
                asm volatile("bar.sync %0, 64;" :: "r"(1 + ks) : "memory");
                #pragma unroll
                for (int kq = 0; kq < 4; kq++) {
                    const int k16 = ph * 4 + kq;
                    const int krow = kbase + k16 * 16 + a_krow;
                    #pragma unroll
                    for (int mi = 0; mi < 2; mi++) {
                        uint32_t off = (uint32_t)((krow * T_STRIDE
                                                   + mi * 16 + a_mh) * 2);
                        uint32_t a0, a1, a2, a3;
                        LDMATRIX_X4_TRANS(a0, a1, a2, a3, sT_u + off);
                        #pragma unroll
                        for (int ni = 0; ni < 4; ni++)
                            MMA_FP16(c[mi][ni], a0, a1, a2, a3,
                                     Wfr[k16][ni][0], Wfr[k16][ni][1]);
                    }
                }
            }

            // store partials: red[wpar][ks][j][33b], scalar stores
            {
                float* rb = red + wpar * RED_PAR + ks * (32 * 33);
                #pragma unroll
                for (int mi = 0; mi < 2; mi++)
                    #pragma unroll
                    for (int ni = 0; ni < 4; ni++) {
                        int row0 = mi * 16 + (lane >> 2);
                        int col0 = ni * 8 + (lane & 3) * 2;
                        rb[col0 * 33 + row0]           = c[mi][ni][0];
                        rb[(col0 + 1) * 33 + row0]     = c[mi][ni][1];
                        rb[col0 * 33 + row0 + 8]       = c[mi][ni][2];
                        rb[(col0 + 1) * 33 + row0 + 8] = c[mi][ni][3];
                    }
            }
            __syncthreads();
        }
    } else {
        // ================= PRODUCER: fill + gates warps =================
        const int ks = wid - 8;
        const int kbase = ks << 7;
        const int gb  = tid & 31;
        const int gdl = (tid >> 5) & 7;
        // lane L (<16) polls flag of producer 16ks+L; __syncwarp fence
        // extends each acquire to the whole warp (release->acquire->fence)
        const u64* pollp = (lane < 16) ? &g_flag[16 * ks + lane][0] : (const u64*)0;
        float c_reg = 0.0f;

        for (int s = 0; s < SS; s++) {
            const int rpar = (s + 1) & 1;
            const int wpar = s & 1;

            // xp prefetch
            const float* xpp = g_xp + ((size_t)s * BB + gb) * EE + d0 + gdl;
            float xp0 = __ldg(xpp);
            float xp1 = __ldg(xpp + 1024);
            float xp2 = __ldg(xpp + 2048);
            float xp3 = __ldg(xpp + 3072);

            const __half* src = g_hT[rpar] + kbase * 32;   // contiguous 8KB chunk

            // ---- single discovery round: poll all 16 producers at once ----
            if (lane < 16) {
                u64 v;
                asm volatile("ld.acquire.gpu.global.u64 %0, [%1];"
                             : "=l"(v) : "l"(pollp));
                while (v < (u64)s) {
                    __nanosleep(32);
                    asm volatile("ld.acquire.gpu.global.u64 %0, [%1];"
                                 : "=l"(v) : "l"(pollp));
                }
            }
            __syncwarp();

            // ---- single LDG round: both phases, MLP 16 ----
            uint4 w[16];
            #pragma unroll
            for (int it = 0; it < 16; it++)
                w[it] = __ldcg((const uint4*)(src + (it * 32 + lane) * 8));

            // ---- STS phase 0 (rows kbase..kbase+64), release consumers ----
            #pragma unroll
            for (int it = 0; it < 8; it++) {
                int u = it * 32 + lane;
                int row = kbase + (u >> 2);
                *(uint4*)(sT + (size_t)row * T_STRIDE + (u & 3) * 8) = w[it];
            }
            asm volatile("bar.sync %0, 64;" :: "r"(1 + ks) : "memory");

            // ---- STS phase 1 (rows kbase+64..kbase+128) ----
            #pragma unroll
            for (int it = 8; it < 16; it++) {
                int u = it * 32 + lane;
                int row = kbase + (u >> 2);
                *(uint4*)(sT + (size_t)row * T_STRIDE + (u & 3) * 8) = w[it];
            }
            asm volatile("bar.sync %0, 64;" :: "r"(1 + ks) : "memory");

            __syncthreads();   // consumers finished red[wpar] for step s

            // ---- gates tail ----
            float ht;
            {
                const float* rp = red + wpar * RED_PAR;
                float z0 = xp0, z1 = xp1, z2 = xp2, z3 = xp3;
                #pragma unroll
                for (int kk = 0; kk < 8; kk++) {
                    const float* rb = rp + kk * (32 * 33);
                    z0 += rb[(0 * 8 + gdl) * 33 + gb];
                    z1 += rb[(1 * 8 + gdl) * 33 + gb];
                    z2 += rb[(2 * 8 + gdl) * 33 + gb];
                    z3 += rb[(3 * 8 + gdl) * 33 + gb];
                }
                float it = sigf(z0), ft = sigf(z1), ot = sigf(z2);
                float gt = tanhf_fast(z3);
                float ct = sigf(ft * c_reg + it * gt);   // nonstandard cell (matches ref)
                ht = tanhf_fast(ct) * ot;
                c_reg = ct;
                // TRANSPOSED h store: warp 8+gdl writes 64B contiguous
                g_hT[wpar][(d0 + gdl) * 32 + gb] = __float2half_rn(ht);
            }

            // gates-group barrier (warps 8-15 = 256 threads), publish flag
            asm volatile("bar.sync 9, 256;" ::: "memory");
            if (tid == 256) {
                asm volatile("st.release.gpu.global.u64 [%0], %1;"
                             :: "l"(&g_flag[blockIdx.x][0]), "l"((u64)(s + 1)) : "memory");
            }

            // out store off the critical path (after release)
            out[((size_t)gb * SS + s) * DD + d0 + gdl] = ht;
        }
    }
}

// =====================================================================
// Input order: 0:seq, 1:Ui, 2:Wi, 3:Uf, 4:Wf, 5:Uo, 6:Wo, 7:Ug, 8:Wg,
//              9:bi, 10:bf, 11:bo, 12:bg
// =====================================================================
extern "C" void kernel_launch(void* const* d_in, const int* in_sizes, int n_in,
                              void* d_out, int out_size)
{
    const float* X  = (const float*)d_in[0];
    const float* Ui = (const float*)d_in[1];
    const float* Wi = (const float*)d_in[2];
    const float* Uf = (const float*)d_in[3];
    const float* Wf = (const float*)d_in[4];
    const float* Uo = (const float*)d_in[5];
    const float* Wo = (const float*)d_in[6];
    const float* Ug = (const float*)d_in[7];
    const float* Wg = (const float*)d_in[8];
    const float* bi = (const float*)d_in[9];
    const float* bf = (const float*)d_in[10];
    const float* bo = (const float*)d_in[11];
    const float* bg = (const float*)d_in[12];
    float* out = (float*)d_out;

    // Prep: X -> fp16, transpose U -> fp16
    splitX_kernel<<<(BB * SS * DD) / (256 * 4), 256>>>(X);
    dim3 gt(32, 32, 4);
    transU_kernel<<<gt, 256>>>(Ui, Uf, Uo, Ug);

    // x_proj GEMM (HMMA fp16)
    cudaFuncSetAttribute(xproj_mma,
                         cudaFuncAttributeMaxDynamicSharedMemorySize, XJ_SMEM);
    dim3 g1(EE / 64, (BB * SS) / 128);   // (64, 128)
    xproj_mma<<<g1, 256, XJ_SMEM>>>(bi, bf, bo, bg);

    // Recurrence (HMMA fp16, warp-specialized, single-discovery protocol)
    cudaFuncSetAttribute(lstm_rec_mma,
                         cudaFuncAttributeMaxDynamicSharedMemorySize, REC_SMEM_BYTES);
    lstm_rec_mma<<<NBLK, 512, REC_SMEM_BYTES>>>(Wi, Wf, Wo, Wg, out);
}